// round 12
// baseline (speedup 1.0000x reference)
#include <cuda_runtime.h>
#include <cstdint>
#include <cstring>

#define SQ 512
#define BB 64
#define EE 128
#define HH 256
#define NG 1024   // 4*H

// ---------------- scratch (static device memory; no allocations) ----------------
__device__ float g_x [SQ*BB*EE];          // embedded inputs          16 MB
__device__ float g_xg[(size_t)SQ*BB*NG];  // forward input-gate proj  128 MB
__device__ float g_gb[BB*NG];             // backward first-step gates
__device__ float g_hf[BB*HH];             // final forward h
__device__ float g_hb[BB*HH];             // backward first-step h

typedef unsigned long long ull;

__device__ __forceinline__ void fma2(ull& d, ull a, ull b) {
    asm("fma.rn.f32x2 %0, %1, %2, %0;" : "+l"(d) : "l"(a), "l"(b));
}
__device__ __forceinline__ ull pk(float x, float y) {
    float2 f = make_float2(x, y); ull v; memcpy(&v, &f, 8); return v;
}
__device__ __forceinline__ float2 unpk(ull v) {
    float2 f; memcpy(&f, &v, 8); return f;
}
__device__ __forceinline__ float sigf(float x)  { return 1.f/(1.f+__expf(-x)); }
__device__ __forceinline__ float tanhf_(float x){ return 1.f - 2.f/(__expf(2.f*x)+1.f); }

// ---------------- kernel 1: embedding gather ----------------
__global__ void k_embed(const int* __restrict__ seq, const float* __restrict__ emb,
                        float* __restrict__ x)
{
    int row  = blockIdx.x * 4 + (threadIdx.x >> 5);
    int lane = threadIdx.x & 31;
    int idx  = seq[row];
    float4 v;
    if (idx == 0) v = make_float4(0.f, 0.f, 0.f, 0.f);
    else          v = ((const float4*)emb)[(size_t)idx * 32 + lane];
    ((float4*)x)[(size_t)row * 32 + lane] = v;
}

// ---------------- kernel 2: C[M,1024] = A[M,128] @ W[1024,128]^T + bias ----------------
__global__ void __launch_bounds__(256)
k_gemm(const float* __restrict__ A, const float* __restrict__ W,
       const float* __restrict__ bias, float* __restrict__ C)
{
    extern __shared__ float sm[];
    float* As = sm;             // [128][68]
    float* Bs = sm + 128*68;    // [128][68]

    const int tid = threadIdx.x;
    const int gm0 = blockIdx.y * 64;
    const int gn0 = blockIdx.x * 64;

#pragma unroll
    for (int i = 0; i < 8; ++i) {
        int e   = tid + i * 256;
        int row = e >> 5;
        int kq  = e & 31;
        float4 a = ((const float4*)A)[(size_t)(gm0 + row) * 32 + kq];
        As[(4*kq+0)*68 + row] = a.x;
        As[(4*kq+1)*68 + row] = a.y;
        As[(4*kq+2)*68 + row] = a.z;
        As[(4*kq+3)*68 + row] = a.w;
        float4 w = ((const float4*)W)[(size_t)(gn0 + row) * 32 + kq];
        Bs[(4*kq+0)*68 + row] = w.x;
        Bs[(4*kq+1)*68 + row] = w.y;
        Bs[(4*kq+2)*68 + row] = w.z;
        Bs[(4*kq+3)*68 + row] = w.w;
    }
    __syncthreads();

    const int tx = tid & 15, ty = tid >> 4;
    const int m0 = ty * 4, n0 = tx * 4;

    float b0 = bias[gn0+n0+0], b1 = bias[gn0+n0+1];
    float b2 = bias[gn0+n0+2], b3 = bias[gn0+n0+3];
    ull acc[4][2];
#pragma unroll
    for (int i = 0; i < 4; ++i) { acc[i][0] = pk(b0,b1); acc[i][1] = pk(b2,b3); }

#pragma unroll 4
    for (int k = 0; k < 128; ++k) {
        float4 a4 = *(const float4*)&As[k*68 + m0];
        ulonglong2 bb = *(const ulonglong2*)&Bs[k*68 + n0];
        ull ad;
        ad = pk(a4.x, a4.x); fma2(acc[0][0], ad, bb.x); fma2(acc[0][1], ad, bb.y);
        ad = pk(a4.y, a4.y); fma2(acc[1][0], ad, bb.x); fma2(acc[1][1], ad, bb.y);
        ad = pk(a4.z, a4.z); fma2(acc[2][0], ad, bb.x); fma2(acc[2][1], ad, bb.y);
        ad = pk(a4.w, a4.w); fma2(acc[3][0], ad, bb.x); fma2(acc[3][1], ad, bb.y);
    }

#pragma unroll
    for (int i = 0; i < 4; ++i) {
        float2 lo = unpk(acc[i][0]), hi = unpk(acc[i][1]);
        float4 o = make_float4(lo.x, lo.y, hi.x, hi.y);
        ((float4*)C)[(size_t)(gm0 + m0 + i) * 256 + ((gn0 + n0) >> 2)] = o;
    }
}

// ---------------- kernel 3: forward LSTM scan ----------------
// 32 clusters x 4 CTAs, 512 thr. Cluster = 2 batch; CTA = 64 hidden units.
// Thread = (unit u = tid>>3, k-octant ko = tid&7). i,f weights in regs,
// g,o in conflict-free SMEM. After phase-2, 3x shfl_down gathers 4 units'
// h into lanes 0-7 of each warp; lane l pushes ONE st.shared::cluster.v4
// (batch l&1 -> dest rank l>>1) and does a parallel remote
// mbarrier.arrive.release. Consumers try_wait ONLY on the mbar of the one
// source rank their k-octant reads (thread ko reads h seg ko, produced by
// rank ko>>1). No barrier.cluster in the loop.
//
// Dyn smem (floats): wgs 16384 | wos 16384 | hbuf[2][2][8][36] 1152 | mbar 16
__global__ void __cluster_dims__(4,1,1) __launch_bounds__(512,1)
k_scan(const float* __restrict__ xg, const float* __restrict__ Whh,
       float* __restrict__ hout)
{
    extern __shared__ float sm[];
    float* wgs  = sm;
    float* wos  = sm + 16384;
    float* hbuf = sm + 32768;            // 1152 floats
    // mbars: 8 x u64 at float index 33920 (byte 135680, 8B aligned)

    const int tid   = threadIdx.x;
    const int rank  = blockIdx.x & 3;
    const int bg    = blockIdx.x >> 2;        // 0..31  (2 batch elems each)
    const int jbase = rank << 6;              // 64-unit hidden slice

    const int u    = tid >> 3;                // hidden unit 0..63
    const int ko   = tid & 7;                 // k-octant: k in [32*ko, 32*ko+32)
    const int pb   = ko & 1;                  // phase-2 batch
    const int dr   = ko >> 1;                 // source rank this thread's k-slice needs
    const int w    = tid >> 5;                // warp 0..15
    const int lane = tid & 31;

    const uint32_t smbase  = (uint32_t)__cvta_generic_to_shared(sm);
    const uint32_t mbar0   = smbase + 33920u * 4u;
    const uint32_t hbase   = smbase + 32768u * 4u;

    if (tid < 8)
        asm volatile("mbarrier.init.shared.b64 [%0], 32;"
                     :: "r"(mbar0 + tid * 8) : "memory");

    // ---- weights: i,f rows -> regs; g,o rows -> smem [c][tid] ----
    ull wi[16], wf[16];
    {
        const float4* pi = (const float4*)(Whh + (size_t)(0*HH + jbase + u)*HH + ko*32);
        const float4* pf = (const float4*)(Whh + (size_t)(1*HH + jbase + u)*HH + ko*32);
        const float4* pg = (const float4*)(Whh + (size_t)(2*HH + jbase + u)*HH + ko*32);
        const float4* po = (const float4*)(Whh + (size_t)(3*HH + jbase + u)*HH + ko*32);
#pragma unroll
        for (int c = 0; c < 8; ++c) {
            float4 a = pi[c]; wi[2*c] = pk(a.x, a.y); wi[2*c+1] = pk(a.z, a.w);
            float4 b = pf[c]; wf[2*c] = pk(b.x, b.y); wf[2*c+1] = pk(b.z, b.w);
            ((float4*)wgs)[c*512 + tid] = pg[c];
            ((float4*)wos)[c*512 + tid] = po[c];
        }
    }
    for (int i = tid; i < 1152; i += 512) hbuf[i] = 0.f;

    float creg = 0.f;

    // consumer: local mbar addrs for my source rank, both buffers
    const uint32_t wa0 = mbar0 + (0*4 + dr) * 8;
    const uint32_t wa1 = mbar0 + (1*4 + dr) * 8;

    // producer (lanes 0-7 of each warp): lane l -> (batch l&1, dest rank l>>1),
    // pushing units jbase + w*4 .. +3. Precompute buf-0 addrs; buf-1 = +delta.
    uint32_t pd0 = 0, aa0 = 0;
    if (lane < 8) {
        int ppb = lane & 1;
        int pdr = lane >> 1;
        int k   = jbase + w * 4;
        uint32_t off = (uint32_t)(((ppb)*288 + (k>>5)*36 + (k&31)) * 4);
        asm("mapa.shared::cluster.u32 %0, %1, %2;" : "=r"(pd0) : "r"(hbase + off), "r"(pdr));
        asm("mapa.shared::cluster.u32 %0, %1, %2;" : "=r"(aa0) : "r"(mbar0 + (uint32_t)(rank*8)), "r"(pdr));
    }

    // xg: lane ko loads gate dr, batch pb, for unit u
    const float* xp = xg + (size_t)(2*bg + pb) * NG + dr*HH + jbase + u;
    float nx = xp[0];

    __syncthreads();
    asm volatile("barrier.cluster.arrive.aligned;" ::: "memory");
    asm volatile("barrier.cluster.wait.aligned;"   ::: "memory");

#pragma unroll 1
    for (int t = 0; t < SQ; ++t) {
        if (t) {
            uint32_t wa  = (t & 1) ? wa1 : wa0;
            uint32_t par = (uint32_t)(((t - 1) >> 1) & 1);
            asm volatile(
                "{\n\t.reg .pred P;\n"
                "WLP%=:\n\t"
                "mbarrier.try_wait.parity.acquire.cluster.shared::cta.b64 P, [%0], %1, 0x989680;\n\t"
                "@!P bra WLP%=;\n\t}"
                :: "r"(wa), "r"(par) : "memory");
        }

        const float* hq = hbuf + (t & 1) * 576 + ko * 36;

        ull ai0=0,ai1=0, af0=0,af1=0, ag0=0,ag1=0, ao0=0,ao1=0;
#pragma unroll
        for (int c = 0; c < 8; ++c) {
            ulonglong2 h0 = *(const ulonglong2*)(hq + 4*c);          // batch 0
            ulonglong2 h1 = *(const ulonglong2*)(hq + 288 + 4*c);    // batch 1
            ulonglong2 wg = ((const ulonglong2*)wgs)[c*512 + tid];
            ulonglong2 wo = ((const ulonglong2*)wos)[c*512 + tid];
            ull ia = wi[2*c], ib = wi[2*c+1], fa = wf[2*c], fb = wf[2*c+1];
            fma2(ai0, ia, h0.x); fma2(ai0, ib, h0.y);
            fma2(ai1, ia, h1.x); fma2(ai1, ib, h1.y);
            fma2(af0, fa, h0.x); fma2(af0, fb, h0.y);
            fma2(af1, fa, h1.x); fma2(af1, fb, h1.y);
            fma2(ag0, wg.x, h0.x); fma2(ag0, wg.y, h0.y);
            fma2(ag1, wg.x, h1.x); fma2(ag1, wg.y, h1.y);
            fma2(ao0, wo.x, h0.x); fma2(ao0, wo.y, h0.y);
            fma2(ao1, wo.x, h1.x); fma2(ao1, wo.y, h1.y);
        }

        // pairwise collapse + fold this lane's xg into its (gate dr, batch pb) sum
        float2 f;
        f = unpk(ai0); float si0 = f.x + f.y;
        f = unpk(ai1); float si1 = f.x + f.y;
        f = unpk(af0); float sf0 = f.x + f.y;
        f = unpk(af1); float sf1 = f.x + f.y;
        f = unpk(ag0); float sg0 = f.x + f.y;
        f = unpk(ag1); float sg1 = f.x + f.y;
        f = unpk(ao0); float so0 = f.x + f.y;
        f = unpk(ao1); float so1 = f.x + f.y;
        if      (ko == 0) si0 += nx;
        else if (ko == 1) si1 += nx;
        else if (ko == 2) sf0 += nx;
        else if (ko == 3) sf1 += nx;
        else if (ko == 4) sg0 += nx;
        else if (ko == 5) sg1 += nx;
        else if (ko == 6) so0 += nx;
        else              so1 += nx;

        // 3-stage butterfly over ko: all lanes get all 8 full sums
#pragma unroll
        for (int o = 1; o <= 4; o <<= 1) {
            si0 += __shfl_xor_sync(~0u, si0, o);
            si1 += __shfl_xor_sync(~0u, si1, o);
            sf0 += __shfl_xor_sync(~0u, sf0, o);
            sf1 += __shfl_xor_sync(~0u, sf1, o);
            sg0 += __shfl_xor_sync(~0u, sg0, o);
            sg1 += __shfl_xor_sync(~0u, sg1, o);
            so0 += __shfl_xor_sync(~0u, so0, o);
            so1 += __shfl_xor_sync(~0u, so1, o);
        }

        // phase 2 (4 redundant copies per (unit,batch)), batch pb
        float gi = pb ? si1 : si0;
        float gf = pb ? sf1 : sf0;
        float gg = pb ? sg1 : sg0;
        float go = pb ? so1 : so0;
        float iv = sigf(gi), fv = sigf(gf), cv = tanhf_(gg), ov = sigf(go);
        creg = fv * creg + iv * cv;
        float hv = ov * tanhf_(creg);

        if (t < SQ - 1) {
            // gather 4 units' h into lanes 0-7 (same ko across u = w*4..w*4+3)
            float v1 = __shfl_down_sync(~0u, hv, 8);
            float v2 = __shfl_down_sync(~0u, hv, 16);
            float v3 = __shfl_down_sync(~0u, hv, 24);
            if (lane < 8) {
                const bool b1 = ((t + 1) & 1) != 0;
                uint32_t pd = pd0 + (b1 ? 2304u : 0u);   // hbuf buf stride 576 floats
                uint32_t aa = aa0 + (b1 ? 32u   : 0u);   // mbar buf stride 4 mbars
                asm volatile("st.shared::cluster.v4.f32 [%0], {%1, %2, %3, %4};"
                             :: "r"(pd), "f"(hv), "f"(v1), "f"(v2), "f"(v3) : "memory");
                asm volatile("mbarrier.arrive.release.cluster.shared::cluster.b64 _, [%0];"
                             :: "r"(aa) : "memory");
            }
            // prefetch next xg under the exchange
            nx = xp[(size_t)(t + 1) * (BB * NG)];
        } else {
            if (ko < 2)
                hout[(size_t)(2*bg + pb) * HH + jbase + u] = hv;
        }
    }

    // drain before exit (no remote traffic may target an exited CTA)
    asm volatile("barrier.cluster.arrive.aligned;" ::: "memory");
    asm volatile("barrier.cluster.wait.aligned;"   ::: "memory");
}

// ---------------- kernel 4: backward first-step (h0=c0=0) ----------------
__global__ void k_hback(const float* __restrict__ gb, float* __restrict__ hb)
{
    int i = blockIdx.x * 256 + threadIdx.x;
    int b = i >> 8, j = i & 255;
    const float* g = gb + (size_t)b * NG;
    float iv = sigf(g[j]);
    float gv = tanhf_(g[512 + j]);
    float ov = sigf(g[768 + j]);
    float c  = iv * gv;
    hb[i] = ov * tanhf_(c);
}

// ---------------- kernel 5: output head (warp per batch elem) ----------------
__global__ void k_out(const float* __restrict__ hf, const float* __restrict__ hb,
                      const float* __restrict__ Wout, const float* __restrict__ bout,
                      float* __restrict__ out)
{
    int b = blockIdx.x, lane = threadIdx.x;
    const float4* hf4 = (const float4*)(hf + (size_t)b * HH);
    const float4* hb4 = (const float4*)(hb + (size_t)b * HH);
    const float4* wA  = (const float4*)Wout;
    const float4* wB  = (const float4*)(Wout + HH);
    float acc = 0.f;
#pragma unroll
    for (int i = 0; i < 2; ++i) {
        int idx = lane + 32*i;
        float4 a = hf4[idx], w = wA[idx];
        acc += a.x*w.x + a.y*w.y + a.z*w.z + a.w*w.w;
        float4 c = hb4[idx], v = wB[idx];
        acc += c.x*v.x + c.y*v.y + c.z*v.z + c.w*v.w;
    }
#pragma unroll
    for (int o = 16; o; o >>= 1) acc += __shfl_xor_sync(~0u, acc, o);
    if (lane == 0) out[b] = sigf(acc + bout[0]);
}

// ---------------- launch ----------------
extern "C" void kernel_launch(void* const* d_in, const int* in_sizes, int n_in,
                              void* d_out, int out_size)
{
    (void)in_sizes; (void)n_in; (void)out_size;
    const int*   seq  = (const int*)  d_in[0];
    const float* emb  = (const float*)d_in[1];
    const float* Wihf = (const float*)d_in[2];
    const float* Whhf = (const float*)d_in[3];
    const float* bf   = (const float*)d_in[4];
    const float* Wihb = (const float*)d_in[5];
    const float* Whhb = (const float*)d_in[6];
    const float* bb   = (const float*)d_in[7];
    const float* Wout = (const float*)d_in[8];
    const float* bout = (const float*)d_in[9];
    (void)Whhb;
    float* out = (float*)d_out;

    float *x, *xgf, *gb, *hf, *hb;
    cudaGetSymbolAddress((void**)&x,   g_x);
    cudaGetSymbolAddress((void**)&xgf, g_xg);
    cudaGetSymbolAddress((void**)&gb,  g_gb);
    cudaGetSymbolAddress((void**)&hf,  g_hf);
    cudaGetSymbolAddress((void**)&hb,  g_hb);

    const int SMEM_GEMM = 2 * 128 * 68 * 4;                  // 69632
    const int SMEM_SCAN = (33920 + 16) * 4;                  // 135744 (incl. 8 mbars)
    cudaFuncSetAttribute(k_gemm, cudaFuncAttributeMaxDynamicSharedMemorySize, SMEM_GEMM);
    cudaFuncSetAttribute(k_scan, cudaFuncAttributeMaxDynamicSharedMemorySize, SMEM_SCAN);

    k_embed<<<SQ*BB/4, 128>>>(seq, emb, x);
    dim3 g2(16, SQ*BB/64);
    k_gemm<<<g2, 256, SMEM_GEMM>>>(x, Wihf, bf, xgf);
    dim3 g2b(16, 1);
    k_gemm<<<g2b, 256, SMEM_GEMM>>>(x + (size_t)(SQ-1)*BB*EE, Wihb, bb, gb);
    k_scan<<<128, 512, SMEM_SCAN>>>(xgf, Whhf, hf);
    k_hback<<<64, 256>>>(gb, hb);
    k_out<<<64, 32>>>(hf, hb, Wout, bout, out);
}

// round 13
// speedup vs baseline: 2.6079x; 2.6079x over previous
#include <cuda_runtime.h>
#include <cstdint>
#include <cstring>

#define SQ 512
#define BB 64
#define EE 128
#define HH 256
#define NG 1024   // 4*H

// ---------------- scratch (static device memory; no allocations) ----------------
__device__ float g_x [SQ*BB*EE];          // embedded inputs          16 MB
__device__ float g_xg[(size_t)SQ*BB*NG];  // forward input-gate proj  128 MB
__device__ float g_gb[BB*NG];             // backward first-step gates
__device__ float g_hf[BB*HH];             // final forward h
__device__ float g_hb[BB*HH];             // backward first-step h

typedef unsigned long long ull;

__device__ __forceinline__ void fma2(ull& d, ull a, ull b) {
    asm("fma.rn.f32x2 %0, %1, %2, %0;" : "+l"(d) : "l"(a), "l"(b));
}
__device__ __forceinline__ ull pk(float x, float y) {
    float2 f = make_float2(x, y); ull v; memcpy(&v, &f, 8); return v;
}
__device__ __forceinline__ float2 unpk(ull v) {
    float2 f; memcpy(&f, &v, 8); return f;
}
__device__ __forceinline__ float sigf(float x)  { return 1.f/(1.f+__expf(-x)); }
__device__ __forceinline__ float tanhf_(float x){ return 1.f - 2.f/(__expf(2.f*x)+1.f); }

// ---------------- kernel 1: embedding gather ----------------
__global__ void k_embed(const int* __restrict__ seq, const float* __restrict__ emb,
                        float* __restrict__ x)
{
    int row  = blockIdx.x * 4 + (threadIdx.x >> 5);
    int lane = threadIdx.x & 31;
    int idx  = seq[row];
    float4 v;
    if (idx == 0) v = make_float4(0.f, 0.f, 0.f, 0.f);
    else          v = ((const float4*)emb)[(size_t)idx * 32 + lane];
    ((float4*)x)[(size_t)row * 32 + lane] = v;
}

// ---------------- kernel 2: C[M,1024] = A[M,128] @ W[1024,128]^T + bias ----------------
__global__ void __launch_bounds__(256)
k_gemm(const float* __restrict__ A, const float* __restrict__ W,
       const float* __restrict__ bias, float* __restrict__ C)
{
    extern __shared__ float sm[];
    float* As = sm;             // [128][68]
    float* Bs = sm + 128*68;    // [128][68]

    const int tid = threadIdx.x;
    const int gm0 = blockIdx.y * 64;
    const int gn0 = blockIdx.x * 64;

#pragma unroll
    for (int i = 0; i < 8; ++i) {
        int e   = tid + i * 256;
        int row = e >> 5;
        int kq  = e & 31;
        float4 a = ((const float4*)A)[(size_t)(gm0 + row) * 32 + kq];
        As[(4*kq+0)*68 + row] = a.x;
        As[(4*kq+1)*68 + row] = a.y;
        As[(4*kq+2)*68 + row] = a.z;
        As[(4*kq+3)*68 + row] = a.w;
        float4 w = ((const float4*)W)[(size_t)(gn0 + row) * 32 + kq];
        Bs[(4*kq+0)*68 + row] = w.x;
        Bs[(4*kq+1)*68 + row] = w.y;
        Bs[(4*kq+2)*68 + row] = w.z;
        Bs[(4*kq+3)*68 + row] = w.w;
    }
    __syncthreads();

    const int tx = tid & 15, ty = tid >> 4;
    const int m0 = ty * 4, n0 = tx * 4;

    float b0 = bias[gn0+n0+0], b1 = bias[gn0+n0+1];
    float b2 = bias[gn0+n0+2], b3 = bias[gn0+n0+3];
    ull acc[4][2];
#pragma unroll
    for (int i = 0; i < 4; ++i) { acc[i][0] = pk(b0,b1); acc[i][1] = pk(b2,b3); }

#pragma unroll 4
    for (int k = 0; k < 128; ++k) {
        float4 a4 = *(const float4*)&As[k*68 + m0];
        ulonglong2 bb = *(const ulonglong2*)&Bs[k*68 + n0];
        ull ad;
        ad = pk(a4.x, a4.x); fma2(acc[0][0], ad, bb.x); fma2(acc[0][1], ad, bb.y);
        ad = pk(a4.y, a4.y); fma2(acc[1][0], ad, bb.x); fma2(acc[1][1], ad, bb.y);
        ad = pk(a4.z, a4.z); fma2(acc[2][0], ad, bb.x); fma2(acc[2][1], ad, bb.y);
        ad = pk(a4.w, a4.w); fma2(acc[3][0], ad, bb.x); fma2(acc[3][1], ad, bb.y);
    }

#pragma unroll
    for (int i = 0; i < 4; ++i) {
        float2 lo = unpk(acc[i][0]), hi = unpk(acc[i][1]);
        float4 o = make_float4(lo.x, lo.y, hi.x, hi.y);
        ((float4*)C)[(size_t)(gm0 + m0 + i) * 256 + ((gn0 + n0) >> 2)] = o;
    }
}

// ---------------- kernel 3: forward LSTM scan ----------------
// R10 base (best: 1566us) + ONE delta: wide v4 shfl-gather exchange (proven
// in R12 to cut receiver L1 pressure 43.5%->27.6%).
// 32 clusters x 4 CTAs, 256 thr. Cluster = 2 batch; CTA = 64 hidden units.
// Thread = (unit rp = tid>>2, kq = tid&3). i,f weights in regs; g,o in
// conflict-free SMEM. Butterfly leaves all 4 gate sums in every lane; each
// lane runs phase-2 for batch kq&1. Exchange: 4 shfl gather 4-unit runs of
// h into lanes 0-15 of each warp; lane l = (rank l&3, batch (l>>2)&1,
// unit-half l>>3) pushes ONE st.shared::cluster.v4. barrier.cluster split:
// arrive after push, xg prefetch in its shadow, wait at next step's top.
//
// Dyn smem (floats): wgs 16384 | wos 16384 | hbuf[2 buf][2 b][272] 1088
__global__ void __cluster_dims__(4,1,1) __launch_bounds__(256,1)
k_scan(const float* __restrict__ xg, const float* __restrict__ Whh,
       float* __restrict__ hout)
{
    extern __shared__ float sm[];
    float* wgs  = sm;
    float* wos  = sm + 16384;
    float* hbuf = sm + 32768;

    const int tid   = threadIdx.x;
    const int rank  = blockIdx.x & 3;
    const int bg    = blockIdx.x >> 2;        // 0..31  (2 batch elems each)
    const int jbase = rank << 6;              // 64-unit hidden slice

    const int rp = tid >> 2;                  // hidden unit 0..63
    const int kq = tid & 3;                   // k in [64*kq, 64*kq+64)
    const int w  = tid >> 5;                  // warp 0..7 (units w*8..w*8+7)
    const int L  = tid & 31;                  // lane

    // ---- weights: i,f rows -> regs; g,o rows -> smem [c][tid] ----
    ull wi[32], wf[32];
    {
        const float4* pi = (const float4*)(Whh + (size_t)(0*HH + jbase + rp)*HH + kq*64);
        const float4* pf = (const float4*)(Whh + (size_t)(1*HH + jbase + rp)*HH + kq*64);
        const float4* pg = (const float4*)(Whh + (size_t)(2*HH + jbase + rp)*HH + kq*64);
        const float4* po = (const float4*)(Whh + (size_t)(3*HH + jbase + rp)*HH + kq*64);
#pragma unroll
        for (int c = 0; c < 16; ++c) {
            float4 a = pi[c]; wi[2*c] = pk(a.x, a.y); wi[2*c+1] = pk(a.z, a.w);
            float4 b = pf[c]; wf[2*c] = pk(b.x, b.y); wf[2*c+1] = pk(b.z, b.w);
            ((float4*)wgs)[c*256 + tid] = pg[c];
            ((float4*)wos)[c*256 + tid] = po[c];
        }
    }
    for (int i = tid; i < 1088; i += 256) hbuf[i] = 0.f;

    // ---- per-thread phase-2 identity: batch pb = kq&1, unit rp ----
    const int pb = kq & 1;
    float creg = 0.f;

    // ---- push config (lanes 0-15 of each warp): lane L ->
    //      dest rank r = L&3, batch b = (L>>2)&1, unit-half hh = L>>3 ----
    uint32_t pa0 = 0, pa1 = 0;
    {
        int r  = L & 3;
        int b  = (L >> 2) & 1;
        int hh = (L >> 3) & 1;
        uint32_t hb32 = (uint32_t)__cvta_generic_to_shared(hbuf);
        uint32_t o0 = (uint32_t)(((0*2 + b)*272 + rank*68 + w*8 + hh*4) * 4);
        uint32_t o1 = (uint32_t)(((1*2 + b)*272 + rank*68 + w*8 + hh*4) * 4);
        asm("mapa.shared::cluster.u32 %0, %1, %2;" : "=r"(pa0) : "r"(hb32+o0), "r"(r));
        asm("mapa.shared::cluster.u32 %0, %1, %2;" : "=r"(pa1) : "r"(hb32+o1), "r"(r));
    }
    // shfl gather base: value for unit w*8 + hh*4 + i, batch b sits at
    // within-warp lane (hh*4+i)*4 + b  (choose the kq==b copy)
    const int gbase = ((L >> 3) & 1) * 16 + ((L >> 2) & 1);

    // xg pointers: lane kq loads gate-kq xg for its hidden unit, both batches
    const float* xp0 = xg + (size_t)(2*bg + 0) * NG + kq*HH + jbase + rp;
    const float* xp1 = xg + (size_t)(2*bg + 1) * NG + kq*HH + jbase + rp;
    float nx0 = xp0[0], nx1 = xp1[0];

    __syncthreads();
    asm volatile("barrier.cluster.arrive.aligned;" ::: "memory");
    asm volatile("barrier.cluster.wait.aligned;"   ::: "memory");

#pragma unroll 1
    for (int t = 0; t < SQ; ++t) {
        if (t) asm volatile("barrier.cluster.wait.aligned;" ::: "memory");

        const float* hq = hbuf + (t & 1) * 544 + kq * 68;

        ull ai0=0,ai1=0, af0=0,af1=0, ag0=0,ag1=0, ao0=0,ao1=0;
#pragma unroll
        for (int c = 0; c < 16; ++c) {
            ulonglong2 h0 = *(const ulonglong2*)(hq + 4*c);
            ulonglong2 h1 = *(const ulonglong2*)(hq + 272 + 4*c);
            ulonglong2 wg = ((const ulonglong2*)wgs)[c*256 + tid];
            ulonglong2 wo = ((const ulonglong2*)wos)[c*256 + tid];
            ull ia = wi[2*c], ib = wi[2*c+1], fa = wf[2*c], fb = wf[2*c+1];
            fma2(ai0, ia, h0.x); fma2(ai0, ib, h0.y);
            fma2(ai1, ia, h1.x); fma2(ai1, ib, h1.y);
            fma2(af0, fa, h0.x); fma2(af0, fb, h0.y);
            fma2(af1, fa, h1.x); fma2(af1, fb, h1.y);
            fma2(ag0, wg.x, h0.x); fma2(ag0, wg.y, h0.y);
            fma2(ag1, wg.x, h1.x); fma2(ag1, wg.y, h1.y);
            fma2(ao0, wo.x, h0.x); fma2(ao0, wo.y, h0.y);
            fma2(ao1, wo.x, h1.x); fma2(ao1, wo.y, h1.y);
        }

        // pairwise collapse + fold xg into own gate's sums (pre-butterfly)
        float2 f;
        f = unpk(ai0); float si0 = f.x + f.y;
        f = unpk(ai1); float si1 = f.x + f.y;
        f = unpk(af0); float sf0 = f.x + f.y;
        f = unpk(af1); float sf1 = f.x + f.y;
        f = unpk(ag0); float sg0 = f.x + f.y;
        f = unpk(ag1); float sg1 = f.x + f.y;
        f = unpk(ao0); float so0 = f.x + f.y;
        f = unpk(ao1); float so1 = f.x + f.y;
        if      (kq == 0) { si0 += nx0; si1 += nx1; }
        else if (kq == 1) { sf0 += nx0; sf1 += nx1; }
        else if (kq == 2) { sg0 += nx0; sg1 += nx1; }
        else              { so0 += nx0; so1 += nx1; }

        // butterfly: afterwards EVERY lane of the 4-group has all 8 sums
        si0 += __shfl_xor_sync(~0u, si0, 1); si0 += __shfl_xor_sync(~0u, si0, 2);
        si1 += __shfl_xor_sync(~0u, si1, 1); si1 += __shfl_xor_sync(~0u, si1, 2);
        sf0 += __shfl_xor_sync(~0u, sf0, 1); sf0 += __shfl_xor_sync(~0u, sf0, 2);
        sf1 += __shfl_xor_sync(~0u, sf1, 1); sf1 += __shfl_xor_sync(~0u, sf1, 2);
        sg0 += __shfl_xor_sync(~0u, sg0, 1); sg0 += __shfl_xor_sync(~0u, sg0, 2);
        sg1 += __shfl_xor_sync(~0u, sg1, 1); sg1 += __shfl_xor_sync(~0u, sg1, 2);
        so0 += __shfl_xor_sync(~0u, so0, 1); so0 += __shfl_xor_sync(~0u, so0, 2);
        so1 += __shfl_xor_sync(~0u, so1, 1); so1 += __shfl_xor_sync(~0u, so1, 2);

        // phase 2 (redundant copy per kq pair), batch pb = kq&1
        float gi = pb ? si1 : si0;
        float gf = pb ? sf1 : sf0;
        float gg = pb ? sg1 : sg0;
        float go = pb ? so1 : so0;
        float iv = sigf(gi), fv = sigf(gf), cv = tanhf_(gg), ov = sigf(go);
        creg = fv * creg + iv * cv;
        float hv = ov * tanhf_(creg);

        if (t < SQ - 1) {
            // gather 4 consecutive units' h (same batch) into push lanes
            float v0 = __shfl_sync(~0u, hv, gbase);
            float v1 = __shfl_sync(~0u, hv, gbase + 4);
            float v2 = __shfl_sync(~0u, hv, gbase + 8);
            float v3 = __shfl_sync(~0u, hv, gbase + 12);
            if (L < 16) {
                uint32_t a = ((t & 1) == 0) ? pa1 : pa0;   // write buffer (t+1)&1
                asm volatile("st.shared::cluster.v4.f32 [%0], {%1, %2, %3, %4};"
                             :: "r"(a), "f"(v0), "f"(v1), "f"(v2), "f"(v3) : "memory");
            }
            asm volatile("barrier.cluster.arrive.aligned;" ::: "memory");
            // prefetch next xg in the barrier's shadow
            nx0 = xp0[(size_t)(t + 1) * (BB * NG)];
            nx1 = xp1[(size_t)(t + 1) * (BB * NG)];
        } else {
            if (kq < 2)
                hout[(size_t)(2*bg + pb) * HH + jbase + rp] = hv;
        }
    }
}

// ---------------- kernel 4: backward first-step (h0=c0=0) ----------------
__global__ void k_hback(const float* __restrict__ gb, float* __restrict__ hb)
{
    int i = blockIdx.x * 256 + threadIdx.x;
    int b = i >> 8, j = i & 255;
    const float* g = gb + (size_t)b * NG;
    float iv = sigf(g[j]);
    float gv = tanhf_(g[512 + j]);
    float ov = sigf(g[768 + j]);
    float c  = iv * gv;
    hb[i] = ov * tanhf_(c);
}

// ---------------- kernel 5: output head (warp per batch elem) ----------------
__global__ void k_out(const float* __restrict__ hf, const float* __restrict__ hb,
                      const float* __restrict__ Wout, const float* __restrict__ bout,
                      float* __restrict__ out)
{
    int b = blockIdx.x, lane = threadIdx.x;
    const float4* hf4 = (const float4*)(hf + (size_t)b * HH);
    const float4* hb4 = (const float4*)(hb + (size_t)b * HH);
    const float4* wA  = (const float4*)Wout;
    const float4* wB  = (const float4*)(Wout + HH);
    float acc = 0.f;
#pragma unroll
    for (int i = 0; i < 2; ++i) {
        int idx = lane + 32*i;
        float4 a = hf4[idx], w = wA[idx];
        acc += a.x*w.x + a.y*w.y + a.z*w.z + a.w*w.w;
        float4 c = hb4[idx], v = wB[idx];
        acc += c.x*v.x + c.y*v.y + c.z*v.z + c.w*v.w;
    }
#pragma unroll
    for (int o = 16; o; o >>= 1) acc += __shfl_xor_sync(~0u, acc, o);
    if (lane == 0) out[b] = sigf(acc + bout[0]);
}

// ---------------- launch ----------------
extern "C" void kernel_launch(void* const* d_in, const int* in_sizes, int n_in,
                              void* d_out, int out_size)
{
    (void)in_sizes; (void)n_in; (void)out_size;
    const int*   seq  = (const int*)  d_in[0];
    const float* emb  = (const float*)d_in[1];
    const float* Wihf = (const float*)d_in[2];
    const float* Whhf = (const float*)d_in[3];
    const float* bf   = (const float*)d_in[4];
    const float* Wihb = (const float*)d_in[5];
    const float* Whhb = (const float*)d_in[6];
    const float* bb   = (const float*)d_in[7];
    const float* Wout = (const float*)d_in[8];
    const float* bout = (const float*)d_in[9];
    (void)Whhb;
    float* out = (float*)d_out;

    float *x, *xgf, *gb, *hf, *hb;
    cudaGetSymbolAddress((void**)&x,   g_x);
    cudaGetSymbolAddress((void**)&xgf, g_xg);
    cudaGetSymbolAddress((void**)&gb,  g_gb);
    cudaGetSymbolAddress((void**)&hf,  g_hf);
    cudaGetSymbolAddress((void**)&hb,  g_hb);

    const int SMEM_GEMM = 2 * 128 * 68 * 4;                  // 69632
    const int SMEM_SCAN = (16384*2 + 1088) * 4;              // 135424
    cudaFuncSetAttribute(k_gemm, cudaFuncAttributeMaxDynamicSharedMemorySize, SMEM_GEMM);
    cudaFuncSetAttribute(k_scan, cudaFuncAttributeMaxDynamicSharedMemorySize, SMEM_SCAN);

    k_embed<<<SQ*BB/4, 128>>>(seq, emb, x);
    dim3 g2(16, SQ*BB/64);
    k_gemm<<<g2, 256, SMEM_GEMM>>>(x, Wihf, bf, xgf);
    dim3 g2b(16, 1);
    k_gemm<<<g2b, 256, SMEM_GEMM>>>(x + (size_t)(SQ-1)*BB*EE, Wihb, bb, gb);
    k_scan<<<128, 256, SMEM_SCAN>>>(xgf, Whhf, hf);
    k_hback<<<64, 256>>>(gb, hb);
    k_out<<<64, 32>>>(hf, hb, Wout, bout, out);
}

// round 14
// speedup vs baseline: 2.6806x; 1.0279x over previous
#include <cuda_runtime.h>
#include <cstdint>
#include <cstring>

#define SQ 512
#define BB 64
#define EE 128
#define HH 256
#define NG 1024   // 4*H

// ---------------- scratch (static device memory; no allocations) ----------------
__device__ float g_x [SQ*BB*EE];          // embedded inputs          16 MB
__device__ float g_xg[(size_t)SQ*BB*NG];  // forward input-gate proj  128 MB
__device__ float g_gb[BB*NG];             // backward first-step gates
__device__ float g_hf[BB*HH];             // final forward h
__device__ float g_hb[BB*HH];             // backward first-step h

typedef unsigned long long ull;

__device__ __forceinline__ void fma2(ull& d, ull a, ull b) {
    asm("fma.rn.f32x2 %0, %1, %2, %0;" : "+l"(d) : "l"(a), "l"(b));
}
__device__ __forceinline__ ull pk(float x, float y) {
    float2 f = make_float2(x, y); ull v; memcpy(&v, &f, 8); return v;
}
__device__ __forceinline__ float2 unpk(ull v) {
    float2 f; memcpy(&f, &v, 8); return f;
}
__device__ __forceinline__ float sigf(float x)  { return 1.f/(1.f+__expf(-x)); }
__device__ __forceinline__ float tanhf_(float x){ return 1.f - 2.f/(__expf(2.f*x)+1.f); }

// round-to-nearest-even fp32 -> bf16 bits (load-time only)
__device__ __forceinline__ uint32_t bfbits(float x) {
    uint32_t b = __float_as_uint(x);
    return (b + 0x7fffu + ((b >> 16) & 1u)) >> 16;
}
// two consecutive-k bf16 (lo=k, hi=k+1) -> f32x2 ull {lo: k, hi: k+1}
__device__ __forceinline__ ull bf2ull(uint32_t p) {
    return ((ull)(p & 0xffff0000u) << 32) | (ull)(p << 16);
}

// ---------------- kernel 1: embedding gather ----------------
__global__ void k_embed(const int* __restrict__ seq, const float* __restrict__ emb,
                        float* __restrict__ x)
{
    int row  = blockIdx.x * 4 + (threadIdx.x >> 5);
    int lane = threadIdx.x & 31;
    int idx  = seq[row];
    float4 v;
    if (idx == 0) v = make_float4(0.f, 0.f, 0.f, 0.f);
    else          v = ((const float4*)emb)[(size_t)idx * 32 + lane];
    ((float4*)x)[(size_t)row * 32 + lane] = v;
}

// ---------------- kernel 2a: big GEMM, 128x128 tiles, 8x8 micro, f32x2 ----------------
// C[M,1024] = A[M,128] @ W[1024,128]^T + bias, M multiple of 128
__global__ void __launch_bounds__(256)
k_gemm128(const float* __restrict__ A, const float* __restrict__ W,
          const float* __restrict__ bias, float* __restrict__ C)
{
    extern __shared__ float sm[];
    float* As = sm;              // [128 k][132]  (k-major: As[k][m])
    float* Bs = sm + 128*132;    // [128 k][132]

    const int tid = threadIdx.x;
    const int gm0 = blockIdx.y * 128;
    const int gn0 = blockIdx.x * 128;

#pragma unroll
    for (int i = 0; i < 16; ++i) {
        int e   = tid + i * 256;     // 0..4095
        int row = e >> 5;            // 0..127
        int kq  = e & 31;            // float4 k-chunk
        float4 a = ((const float4*)A)[(size_t)(gm0 + row) * 32 + kq];
        As[(4*kq+0)*132 + row] = a.x;
        As[(4*kq+1)*132 + row] = a.y;
        As[(4*kq+2)*132 + row] = a.z;
        As[(4*kq+3)*132 + row] = a.w;
        float4 w = ((const float4*)W)[(size_t)(gn0 + row) * 32 + kq];
        Bs[(4*kq+0)*132 + row] = w.x;
        Bs[(4*kq+1)*132 + row] = w.y;
        Bs[(4*kq+2)*132 + row] = w.z;
        Bs[(4*kq+3)*132 + row] = w.w;
    }
    __syncthreads();

    const int tx = tid & 15, ty = tid >> 4;
    const int m0 = ty * 8, n0 = tx * 8;

    ull acc[8][4];
#pragma unroll
    for (int j = 0; j < 4; ++j) {
        ull bz = pk(bias[gn0+n0+2*j], bias[gn0+n0+2*j+1]);
#pragma unroll
        for (int i = 0; i < 8; ++i) acc[i][j] = bz;
    }

#pragma unroll 2
    for (int k = 0; k < 128; ++k) {
        float4 aA = *(const float4*)&As[k*132 + m0];
        float4 aB = *(const float4*)&As[k*132 + m0 + 4];
        ulonglong2 b0 = *(const ulonglong2*)&Bs[k*132 + n0];
        ulonglong2 b1 = *(const ulonglong2*)&Bs[k*132 + n0 + 4];
        float av[8] = {aA.x, aA.y, aA.z, aA.w, aB.x, aB.y, aB.z, aB.w};
#pragma unroll
        for (int i = 0; i < 8; ++i) {
            ull ad = pk(av[i], av[i]);
            fma2(acc[i][0], ad, b0.x); fma2(acc[i][1], ad, b0.y);
            fma2(acc[i][2], ad, b1.x); fma2(acc[i][3], ad, b1.y);
        }
    }

#pragma unroll
    for (int i = 0; i < 8; ++i) {
        float2 p0 = unpk(acc[i][0]), p1 = unpk(acc[i][1]);
        float2 p2 = unpk(acc[i][2]), p3 = unpk(acc[i][3]);
        size_t base = (size_t)(gm0 + m0 + i) * 256 + ((gn0 + n0) >> 2);
        ((float4*)C)[base + 0] = make_float4(p0.x, p0.y, p1.x, p1.y);
        ((float4*)C)[base + 1] = make_float4(p2.x, p2.y, p3.x, p3.y);
    }
}

// ---------------- kernel 2b: small GEMM (M=64), 64x64 tiles (proven) ----------------
__global__ void __launch_bounds__(256)
k_gemm(const float* __restrict__ A, const float* __restrict__ W,
       const float* __restrict__ bias, float* __restrict__ C)
{
    extern __shared__ float sm[];
    float* As = sm;             // [128][68]
    float* Bs = sm + 128*68;    // [128][68]

    const int tid = threadIdx.x;
    const int gm0 = blockIdx.y * 64;
    const int gn0 = blockIdx.x * 64;

#pragma unroll
    for (int i = 0; i < 8; ++i) {
        int e   = tid + i * 256;
        int row = e >> 5;
        int kq  = e & 31;
        float4 a = ((const float4*)A)[(size_t)(gm0 + row) * 32 + kq];
        As[(4*kq+0)*68 + row] = a.x;
        As[(4*kq+1)*68 + row] = a.y;
        As[(4*kq+2)*68 + row] = a.z;
        As[(4*kq+3)*68 + row] = a.w;
        float4 w = ((const float4*)W)[(size_t)(gn0 + row) * 32 + kq];
        Bs[(4*kq+0)*68 + row] = w.x;
        Bs[(4*kq+1)*68 + row] = w.y;
        Bs[(4*kq+2)*68 + row] = w.z;
        Bs[(4*kq+3)*68 + row] = w.w;
    }
    __syncthreads();

    const int tx = tid & 15, ty = tid >> 4;
    const int m0 = ty * 4, n0 = tx * 4;

    float b0 = bias[gn0+n0+0], b1 = bias[gn0+n0+1];
    float b2 = bias[gn0+n0+2], b3 = bias[gn0+n0+3];
    ull acc[4][2];
#pragma unroll
    for (int i = 0; i < 4; ++i) { acc[i][0] = pk(b0,b1); acc[i][1] = pk(b2,b3); }

#pragma unroll 4
    for (int k = 0; k < 128; ++k) {
        float4 a4 = *(const float4*)&As[k*68 + m0];
        ulonglong2 bb = *(const ulonglong2*)&Bs[k*68 + n0];
        ull ad;
        ad = pk(a4.x, a4.x); fma2(acc[0][0], ad, bb.x); fma2(acc[0][1], ad, bb.y);
        ad = pk(a4.y, a4.y); fma2(acc[1][0], ad, bb.x); fma2(acc[1][1], ad, bb.y);
        ad = pk(a4.z, a4.z); fma2(acc[2][0], ad, bb.x); fma2(acc[2][1], ad, bb.y);
        ad = pk(a4.w, a4.w); fma2(acc[3][0], ad, bb.x); fma2(acc[3][1], ad, bb.y);
    }

#pragma unroll
    for (int i = 0; i < 4; ++i) {
        float2 lo = unpk(acc[i][0]), hi = unpk(acc[i][1]);
        float4 o = make_float4(lo.x, lo.y, hi.x, hi.y);
        ((float4*)C)[(size_t)(gm0 + m0 + i) * 256 + ((gn0 + n0) >> 2)] = o;
    }
}

// ---------------- kernel 3: forward LSTM scan ----------------
// 32 clusters x 4 CTAs, 512 thr (4 warps/SMSP latency hiding).
// Cluster = 2 batch; CTA = 64 hidden units (256 gate rows).
// Thread = (unit u = tid>>3, k-octant ko = tid&7; 32 k's each).
// i,f weights: fp32 in regs (32 ull). g,o weights: packed bf16 in SMEM —
// one uint4 per (c,tid) carries 4 wg + 4 wo bf16 (halves the crossbar
// stream); exact unpack = shift/and on the idle ALU pipe.
// Butterfly over ko gives all 8 gate sums to every lane; lane runs phase-2
// for batch ko&1. Exchange: shfl-gather + lanes 0-7 push ONE
// st.shared::cluster.v4 (proven R13). Split barrier.cluster.
//
// Dyn smem (floats): wh 16384 (64KB uint4) | hbuf[2][2 b][8 seg][36] 1152
__global__ void __cluster_dims__(4,1,1) __launch_bounds__(512,1)
k_scan(const float* __restrict__ xg, const float* __restrict__ Whh,
       float* __restrict__ hout)
{
    extern __shared__ float sm[];
    uint4* wh   = (uint4*)sm;            // [8 c][512 tid]
    float* hbuf = sm + 16384;

    const int tid   = threadIdx.x;
    const int rank  = blockIdx.x & 3;
    const int bg    = blockIdx.x >> 2;        // 0..31  (2 batch elems each)
    const int jbase = rank << 6;              // 64-unit hidden slice

    const int u  = tid >> 3;                  // hidden unit 0..63
    const int ko = tid & 7;                   // k in [32*ko, 32*ko+32)
    const int pb = ko & 1;                    // phase-2 batch
    const int dr = ko >> 1;                   // xg gate for this lane
    const int w  = tid >> 5;                  // warp 0..15 (units w*4..w*4+3)
    const int L  = tid & 31;

    // ---- weights: i,f -> fp32 regs; g,o -> bf16-packed smem ----
    ull wi[16], wf[16];
    {
        const float4* pi = (const float4*)(Whh + (size_t)(0*HH + jbase + u)*HH + ko*32);
        const float4* pf = (const float4*)(Whh + (size_t)(1*HH + jbase + u)*HH + ko*32);
        const float4* pg = (const float4*)(Whh + (size_t)(2*HH + jbase + u)*HH + ko*32);
        const float4* po = (const float4*)(Whh + (size_t)(3*HH + jbase + u)*HH + ko*32);
#pragma unroll
        for (int c = 0; c < 8; ++c) {
            float4 a = pi[c]; wi[2*c] = pk(a.x, a.y); wi[2*c+1] = pk(a.z, a.w);
            float4 b = pf[c]; wf[2*c] = pk(b.x, b.y); wf[2*c+1] = pk(b.z, b.w);
            float4 g = pg[c]; float4 o = po[c];
            uint4 v;
            v.x = (bfbits(g.y) << 16) | bfbits(g.x);
            v.y = (bfbits(g.w) << 16) | bfbits(g.z);
            v.z = (bfbits(o.y) << 16) | bfbits(o.x);
            v.w = (bfbits(o.w) << 16) | bfbits(o.z);
            wh[c*512 + tid] = v;
        }
    }
    for (int i = tid; i < 1152; i += 512) hbuf[i] = 0.f;

    float creg = 0.f;

    // push addrs (lanes 0-7 per warp): lane l -> (batch l&1, dest rank l>>1),
    // pushing units jbase + w*4 .. +3 (float4-aligned within 36-stride seg)
    uint32_t pa0 = 0, pa1 = 0;
    if (L < 8) {
        int ppb = L & 1;
        int pdr = L >> 1;
        int k0  = jbase + w * 4;
        uint32_t hb32 = (uint32_t)__cvta_generic_to_shared(hbuf);
        uint32_t o0 = (uint32_t)(((0*2 + ppb)*288 + (k0>>5)*36 + (k0&31)) * 4);
        uint32_t o1 = (uint32_t)(((1*2 + ppb)*288 + (k0>>5)*36 + (k0&31)) * 4);
        asm("mapa.shared::cluster.u32 %0, %1, %2;" : "=r"(pa0) : "r"(hb32+o0), "r"(pdr));
        asm("mapa.shared::cluster.u32 %0, %1, %2;" : "=r"(pa1) : "r"(hb32+o1), "r"(pdr));
    }
    // gather: pushing lane l needs h(unit w*4+i, batch l&1) = in-warp lane i*8 + (l&1)
    const int gb = L & 1;   // only meaningful for L<8

    // xg: lane ko loads gate dr, batch pb, for unit u
    const float* xp = xg + (size_t)(2*bg + pb) * NG + dr*HH + jbase + u;
    float nx = xp[0];

    __syncthreads();
    asm volatile("barrier.cluster.arrive.aligned;" ::: "memory");
    asm volatile("barrier.cluster.wait.aligned;"   ::: "memory");

#pragma unroll 1
    for (int t = 0; t < SQ; ++t) {
        if (t) asm volatile("barrier.cluster.wait.aligned;" ::: "memory");

        const float* hq = hbuf + (t & 1) * 576 + ko * 36;

        ull ai0=0,ai1=0, af0=0,af1=0, ag0=0,ag1=0, ao0=0,ao1=0;
#pragma unroll
        for (int c = 0; c < 8; ++c) {
            ulonglong2 h0 = *(const ulonglong2*)(hq + 4*c);          // batch 0
            ulonglong2 h1 = *(const ulonglong2*)(hq + 288 + 4*c);    // batch 1
            uint4 v = wh[c*512 + tid];
            ull ga = bf2ull(v.x), gbu = bf2ull(v.y);
            ull oa = bf2ull(v.z), ob  = bf2ull(v.w);
            ull ia = wi[2*c], ib = wi[2*c+1], fa = wf[2*c], fb = wf[2*c+1];
            fma2(ai0, ia, h0.x); fma2(ai0, ib, h0.y);
            fma2(ai1, ia, h1.x); fma2(ai1, ib, h1.y);
            fma2(af0, fa, h0.x); fma2(af0, fb, h0.y);
            fma2(af1, fa, h1.x); fma2(af1, fb, h1.y);
            fma2(ag0, ga, h0.x); fma2(ag0, gbu, h0.y);
            fma2(ag1, ga, h1.x); fma2(ag1, gbu, h1.y);
            fma2(ao0, oa, h0.x); fma2(ao0, ob, h0.y);
            fma2(ao1, oa, h1.x); fma2(ao1, ob, h1.y);
        }

        // pairwise collapse + fold this lane's xg into its (gate dr, batch pb)
        float2 f;
        f = unpk(ai0); float si0 = f.x + f.y;
        f = unpk(ai1); float si1 = f.x + f.y;
        f = unpk(af0); float sf0 = f.x + f.y;
        f = unpk(af1); float sf1 = f.x + f.y;
        f = unpk(ag0); float sg0 = f.x + f.y;
        f = unpk(ag1); float sg1 = f.x + f.y;
        f = unpk(ao0); float so0 = f.x + f.y;
        f = unpk(ao1); float so1 = f.x + f.y;
        if      (ko == 0) si0 += nx;
        else if (ko == 1) si1 += nx;
        else if (ko == 2) sf0 += nx;
        else if (ko == 3) sf1 += nx;
        else if (ko == 4) sg0 += nx;
        else if (ko == 5) sg1 += nx;
        else if (ko == 6) so0 += nx;
        else              so1 += nx;

        // 3-stage butterfly over ko: all lanes get all 8 full sums
#pragma unroll
        for (int o = 1; o <= 4; o <<= 1) {
            si0 += __shfl_xor_sync(~0u, si0, o);
            si1 += __shfl_xor_sync(~0u, si1, o);
            sf0 += __shfl_xor_sync(~0u, sf0, o);
            sf1 += __shfl_xor_sync(~0u, sf1, o);
            sg0 += __shfl_xor_sync(~0u, sg0, o);
            sg1 += __shfl_xor_sync(~0u, sg1, o);
            so0 += __shfl_xor_sync(~0u, so0, o);
            so1 += __shfl_xor_sync(~0u, so1, o);
        }

        // phase 2 (redundant copies per (unit,batch)), batch pb
        float gi = pb ? si1 : si0;
        float gf = pb ? sf1 : sf0;
        float gg = pb ? sg1 : sg0;
        float go = pb ? so1 : so0;
        float iv = sigf(gi), fv = sigf(gf), cv = tanhf_(gg), ov = sigf(go);
        creg = fv * creg + iv * cv;
        float hv = ov * tanhf_(creg);

        if (t < SQ - 1) {
            // gather 4 units' h (batch gb) into lanes 0-7
            float v0 = __shfl_sync(~0u, hv, 0*8 + gb);
            float v1 = __shfl_sync(~0u, hv, 1*8 + gb);
            float v2 = __shfl_sync(~0u, hv, 2*8 + gb);
            float v3 = __shfl_sync(~0u, hv, 3*8 + gb);
            if (L < 8) {
                uint32_t a = ((t & 1) == 0) ? pa1 : pa0;   // write buffer (t+1)&1
                asm volatile("st.shared::cluster.v4.f32 [%0], {%1, %2, %3, %4};"
                             :: "r"(a), "f"(v0), "f"(v1), "f"(v2), "f"(v3) : "memory");
            }
            asm volatile("barrier.cluster.arrive.aligned;" ::: "memory");
            // prefetch next xg in the barrier's shadow
            nx = xp[(size_t)(t + 1) * (BB * NG)];
        } else {
            if (ko < 2)
                hout[(size_t)(2*bg + pb) * HH + jbase + u] = hv;
        }
    }
}

// ---------------- kernel 4: backward first-step (h0=c0=0) ----------------
__global__ void k_hback(const float* __restrict__ gb, float* __restrict__ hb)
{
    int i = blockIdx.x * 256 + threadIdx.x;
    int b = i >> 8, j = i & 255;
    const float* g = gb + (size_t)b * NG;
    float iv = sigf(g[j]);
    float gv = tanhf_(g[512 + j]);
    float ov = sigf(g[768 + j]);
    float c  = iv * gv;
    hb[i] = ov * tanhf_(c);
}

// ---------------- kernel 5: output head (warp per batch elem) ----------------
__global__ void k_out(const float* __restrict__ hf, const float* __restrict__ hb,
                      const float* __restrict__ Wout, const float* __restrict__ bout,
                      float* __restrict__ out)
{
    int b = blockIdx.x, lane = threadIdx.x;
    const float4* hf4 = (const float4*)(hf + (size_t)b * HH);
    const float4* hb4 = (const float4*)(hb + (size_t)b * HH);
    const float4* wA  = (const float4*)Wout;
    const float4* wB  = (const float4*)(Wout + HH);
    float acc = 0.f;
#pragma unroll
    for (int i = 0; i < 2; ++i) {
        int idx = lane + 32*i;
        float4 a = hf4[idx], w = wA[idx];
        acc += a.x*w.x + a.y*w.y + a.z*w.z + a.w*w.w;
        float4 c = hb4[idx], v = wB[idx];
        acc += c.x*v.x + c.y*v.y + c.z*v.z + c.w*v.w;
    }
#pragma unroll
    for (int o = 16; o; o >>= 1) acc += __shfl_xor_sync(~0u, acc, o);
    if (lane == 0) out[b] = sigf(acc + bout[0]);
}

// ---------------- launch ----------------
extern "C" void kernel_launch(void* const* d_in, const int* in_sizes, int n_in,
                              void* d_out, int out_size)
{
    (void)in_sizes; (void)n_in; (void)out_size;
    const int*   seq  = (const int*)  d_in[0];
    const float* emb  = (const float*)d_in[1];
    const float* Wihf = (const float*)d_in[2];
    const float* Whhf = (const float*)d_in[3];
    const float* bf   = (const float*)d_in[4];
    const float* Wihb = (const float*)d_in[5];
    const float* Whhb = (const float*)d_in[6];
    const float* bb   = (const float*)d_in[7];
    const float* Wout = (const float*)d_in[8];
    const float* bout = (const float*)d_in[9];
    (void)Whhb;
    float* out = (float*)d_out;

    float *x, *xgf, *gb, *hf, *hb;
    cudaGetSymbolAddress((void**)&x,   g_x);
    cudaGetSymbolAddress((void**)&xgf, g_xg);
    cudaGetSymbolAddress((void**)&gb,  g_gb);
    cudaGetSymbolAddress((void**)&hf,  g_hf);
    cudaGetSymbolAddress((void**)&hb,  g_hb);

    const int SMEM_GEMM  = 2 * 128 * 68 * 4;                 // 69632
    const int SMEM_G128  = 2 * 128 * 132 * 4;                // 135168
    const int SMEM_SCAN  = (16384 + 1152) * 4;               // 70144
    cudaFuncSetAttribute(k_gemm,    cudaFuncAttributeMaxDynamicSharedMemorySize, SMEM_GEMM);
    cudaFuncSetAttribute(k_gemm128, cudaFuncAttributeMaxDynamicSharedMemorySize, SMEM_G128);
    cudaFuncSetAttribute(k_scan,    cudaFuncAttributeMaxDynamicSharedMemorySize, SMEM_SCAN);

    k_embed<<<SQ*BB/4, 128>>>(seq, emb, x);
    dim3 g2(8, SQ*BB/128);
    k_gemm128<<<g2, 256, SMEM_G128>>>(x, Wihf, bf, xgf);
    dim3 g2b(16, 1);
    k_gemm<<<g2b, 256, SMEM_GEMM>>>(x + (size_t)(SQ-1)*BB*EE, Wihb, bb, gb);
    k_scan<<<128, 512, SMEM_SCAN>>>(xgf, Whhf, hf);
    k_hback<<<64, 256>>>(gb, hb);
    k_out<<<64, 32>>>(hf, hb, Wout, bout, out);
}